// round 15
// baseline (speedup 1.0000x reference)
#include <cuda_runtime.h>
#include <stdint.h>

#define N_BOX 32768
#define C_CLS 81
#define K_TOP 4096
#define SCORE_T 0.05f
#define NMS_T 0.5f
#define IMG_W 1333.0f
#define IMG_H 800.0f
#define CLS_OFF 4096.0f

// p in (0.05, 1.0]  =>  float top-16 bits in [0x3D4C, 0x3F80]
#define HIST_LO 0x3D4C
#define HIST_N  565
#define BKT_CAP 2048     // max keys per 16-bit bucket (worst observed ~400)

#define NMS_CAP 256      // max rows per class (mean ~51)

// ---- device state. Invariant: every counter is zero on entry to each call
// (zero-init at load; consume-then-reset within each call thereafter).
__device__ unsigned int g_bktCnt[HIST_N];
__device__ unsigned long long g_bktKeys[HIST_N * BKT_CAP];   // 9.3 MB scratch
__device__ int g_cutBucket;
__device__ int g_base[HIST_N];     // keys in buckets strictly above b

__device__ int g_clsCnt[C_CLS];
__device__ int g_clsRows[C_CLS * NMS_CAP];

__device__ float g_bk[K_TOP][4];
__device__ float g_boff[K_TOP][4];
__device__ float g_area[K_TOP];
__device__ float g_val[K_TOP];
__device__ int   g_label[K_TOP];

__device__ unsigned long long g_removed[64];

__device__ unsigned int g_doneS;   // softmax done-counter (self-resetting)
__device__ unsigned int g_doneN;   // nms done-counter (self-resetting)

// xor-butterfly tree sum — all lanes end with identical bits (VALIDATED)
__device__ __forceinline__ float btree_add(float v) {
    #pragma unroll
    for (int o = 16; o; o >>= 1) v = __fadd_rn(v, __shfl_xor_sync(0xFFFFFFFFu, v, o));
    return v;
}

__device__ __forceinline__ void emit_cand(unsigned vb, unsigned idx) {
    int b = (int)(vb >> 16) - HIST_LO;
    unsigned pos = atomicAdd(&g_bktCnt[b], 1u);
    if (pos < BKT_CAP)
        g_bktKeys[b * BKT_CAP + pos] =
            ((unsigned long long)vb << 32) | (0xFFFFFFFFu - idx);
}

// one warp per row — bitwise model of the Triton/MLIR normalization emitter
// (VALIDATED round 6: rel_err 9.3e-12 — arithmetic is FROZEN).
// Tail: last-finishing block computes the cut bucket + suffix bases
// (threadfence + done-counter; counter self-resets).
__global__ void k_softmax(const float* __restrict__ x) {
    int warp = (blockIdx.x * blockDim.x + threadIdx.x) >> 5;
    int lane = threadIdx.x & 31;
    const float* row = x + (size_t)warp * C_CLS;   // grid covers exactly N_BOX warps

    float v0 = row[lane];
    float v1 = row[lane + 32];
    float v2 = (lane < 17) ? row[lane + 64] : -1e30f;

    float m = fmaxf(fmaxf(v0, v1), v2);
    #pragma unroll
    for (int o = 16; o; o >>= 1) m = fmaxf(m, __shfl_xor_sync(0xFFFFFFFFu, m, o));

    float e0 = expf(__fsub_rn(v0, m));
    float e1 = expf(__fsub_rn(v1, m));
    float e2 = (lane < 17) ? expf(__fsub_rn(v2, m)) : 0.0f;

    float B0 = btree_add(e0);
    float B1 = btree_add(e1);
    float B2 = btree_add(e2);
    float s = __fadd_rn(__fadd_rn(B0, B2), B1);

    float p0 = __fdiv_rn(e0, s);
    float p1 = __fdiv_rn(e1, s);
    float p2 = __fdiv_rn(e2, s);

    unsigned rowbase = (unsigned)warp * C_CLS;
    if ((lane != 0) && (p0 > SCORE_T)) emit_cand(__float_as_uint(p0), rowbase + lane);
    if (p1 > SCORE_T)                  emit_cand(__float_as_uint(p1), rowbase + lane + 32);
    if ((lane < 17) && (p2 > SCORE_T)) emit_cand(__float_as_uint(p2), rowbase + lane + 64);

    // ---- fused findcut: last block only ----
    __shared__ unsigned int s_isLast;
    __shared__ unsigned int h[HIST_N];
    __threadfence();
    if (threadIdx.x == 0) {
        unsigned v = atomicAdd(&g_doneS, 1u);
        s_isLast = (v == gridDim.x - 1) ? 1u : 0u;
    }
    __syncthreads();
    if (s_isLast) {
        if (threadIdx.x == 0) g_doneS = 0u;
        for (int i = threadIdx.x; i < HIST_N; i += blockDim.x) h[i] = g_bktCnt[i];
        __syncthreads();
        if (threadIdx.x == 0) {
            unsigned int acc = 0;
            int b = HIST_N - 1;
            int cut = 0;
            for (; b >= 0; b--) {
                g_base[b] = (int)acc;
                unsigned c = h[b]; if (c > BKT_CAP) c = BKT_CAP;
                acc += c;
                if (acc >= K_TOP) { cut = b; break; }
            }
            g_cutBucket = cut;
        }
    }
}

// one CTA per bucket: exact local rank within bucket (keys unique, shared
// 16-bit prefix), global rank = base[b] + local; decode straight into the
// final sorted slot; build per-class lists.
// Consume-then-reset is race-safe: all threads read kb, __syncthreads, then
// t0 resets — before any early return.
__global__ void k_rankscatter(const float* __restrict__ boxes) {
    __shared__ unsigned long long keys[BKT_CAP];
    int b = blockIdx.x;
    int t = threadIdx.x;
    int kb = (int)g_bktCnt[b];
    __syncthreads();
    if (t == 0) g_bktCnt[b] = 0u;
    if (kb > BKT_CAP) kb = BKT_CAP;
    if (kb == 0 || b < g_cutBucket) return;
    int base = g_base[b];

    for (int i = t; i < kb; i += blockDim.x) keys[i] = g_bktKeys[b * BKT_CAP + i];
    __syncthreads();

    for (int i = t; i < kb; i += blockDim.x) {
        unsigned long long key = keys[i];
        int lr = 0;
        for (int j = 0; j < kb; j++) lr += (keys[j] > key);
        int r = base + lr;
        if (r >= K_TOP) continue;
        unsigned idx = 0xFFFFFFFFu - (unsigned)(key & 0xFFFFFFFFull);
        float val = __uint_as_float((unsigned)(key >> 32));
        int bi = (int)(idx / C_CLS);
        int lb = (int)(idx % C_CLS);
        float x1 = fminf(fmaxf(boxes[bi * 4 + 0], 0.0f), IMG_W - 1.0f);
        float y1 = fminf(fmaxf(boxes[bi * 4 + 1], 0.0f), IMG_H - 1.0f);
        float x2 = fminf(fmaxf(boxes[bi * 4 + 2], 0.0f), IMG_W - 1.0f);
        float y2 = fminf(fmaxf(boxes[bi * 4 + 3], 0.0f), IMG_H - 1.0f);
        g_bk[r][0] = x1; g_bk[r][1] = y1; g_bk[r][2] = x2; g_bk[r][3] = y2;
        g_val[r] = val; g_label[r] = lb;
        float off = __fmul_rn((float)lb, CLS_OFF);
        float ox1 = __fadd_rn(x1, off), oy1 = __fadd_rn(y1, off);
        float ox2 = __fadd_rn(x2, off), oy2 = __fadd_rn(y2, off);
        g_boff[r][0] = ox1; g_boff[r][1] = oy1; g_boff[r][2] = ox2; g_boff[r][3] = oy2;
        g_area[r] = __fmul_rn(__fsub_rn(ox2, ox1), __fsub_rn(oy2, oy1));
        int p = atomicAdd(&g_clsCnt[lb], 1);
        if (p < NMS_CAP) g_clsRows[lb * NMS_CAP + p] = r;
    }
}

// Per-class NMS (one 256-thread block per class; cross-class IoU provably 0)
// + fused output emit in the last-finishing block.
// Greedy chain iterates ONLY rows with outgoing suppression edges (rows
// without edges cannot change the removed state — provably equivalent).
__global__ void k_nms(float* __restrict__ out, int out_size) {
    __shared__ int s_r[NMS_CAP];
    __shared__ int s_rows[NMS_CAP];
    __shared__ float s_box[NMS_CAP][4];
    __shared__ float s_area[NMS_CAP];
    __shared__ unsigned long long s_sup[NMS_CAP][4];
    __shared__ unsigned int s_has[8];
    __shared__ unsigned long long s_rm[4];
    __shared__ unsigned int s_isLast;
    __shared__ unsigned long long s_snap[64];

    int c = blockIdx.x + 1;          // classes 1..80
    int t = threadIdx.x;             // 256 threads

    int k = g_clsCnt[c];
    __syncthreads();                 // all threads read k
    if (t == 0) g_clsCnt[c] = 0;     // consume-then-reset
    if (k > NMS_CAP) k = NMS_CAP;

    if (k > 1) {                     // k uniform per block => uniform branch
        if (t < k) s_r[t] = g_clsRows[c * NMS_CAP + t];
        __syncthreads();

        // order ascending by rank (ranks unique): counting sort, 1 thread/row
        if (t < k) {
            int ri = s_r[t];
            int pos = 0;
            for (int j = 0; j < k; j++) pos += (s_r[j] < ri);
            s_rows[pos] = ri;
        }
        __syncthreads();

        if (t < k) {
            int r = s_rows[t];
            s_box[t][0] = g_boff[r][0]; s_box[t][1] = g_boff[r][1];
            s_box[t][2] = g_boff[r][2]; s_box[t][3] = g_boff[r][3];
            s_area[t] = g_area[r];
        }
        __syncthreads();

        // suppression rows (identical _rn sequence; div only when inter>0 —
        // inter==0 => iou==0 exactly => no suppression, provably identical)
        unsigned long long w0 = 0, w1 = 0, w2 = 0, w3 = 0;
        if (t < k) {
            float x1 = s_box[t][0], y1 = s_box[t][1], x2 = s_box[t][2], y2 = s_box[t][3];
            float ai = s_area[t];
            for (int j = t + 1; j < k; j++) {
                float iw = fmaxf(__fsub_rn(fminf(x2, s_box[j][2]), fmaxf(x1, s_box[j][0])), 0.0f);
                float ih = fmaxf(__fsub_rn(fminf(y2, s_box[j][3]), fmaxf(y1, s_box[j][1])), 0.0f);
                float inter = __fmul_rn(iw, ih);
                if (inter > 0.0f) {
                    float denom = __fadd_rn(__fsub_rn(__fadd_rn(ai, s_area[j]), inter), 1e-9f);
                    if (__fdiv_rn(inter, denom) > NMS_T) {
                        unsigned long long bb = 1ull << (j & 63);
                        switch (j >> 6) { case 0: w0 |= bb; break; case 1: w1 |= bb; break;
                                          case 2: w2 |= bb; break; default: w3 |= bb; break; }
                    }
                }
            }
            s_sup[t][0] = w0; s_sup[t][1] = w1; s_sup[t][2] = w2; s_sup[t][3] = w3;
        }
        bool has = ((w0 | w1 | w2 | w3) != 0ull);   // false for t >= k
        unsigned bal = __ballot_sync(0xFFFFFFFFu, has);
        if ((t & 31) == 0) s_has[t >> 5] = bal;
        __syncthreads();

        // sparse serial greedy chain (thread 0) over edge-bearing rows only
        if (t == 0) {
            unsigned long long r0 = 0, r1 = 0, r2 = 0, r3 = 0;
            for (int w8 = 0; w8 < 8; w8++) {
                unsigned bits = s_has[w8];
                while (bits) {
                    int b = __ffs(bits) - 1;
                    bits &= bits - 1u;
                    int i = w8 * 32 + b;
                    unsigned long long rw = (i < 64) ? r0 : (i < 128) ? r1 : (i < 192) ? r2 : r3;
                    if (!((rw >> (i & 63)) & 1ull)) {
                        r0 |= s_sup[i][0]; r1 |= s_sup[i][1];
                        r2 |= s_sup[i][2]; r3 |= s_sup[i][3];
                    }
                }
            }
            s_rm[0] = r0; s_rm[1] = r1; s_rm[2] = r2; s_rm[3] = r3;
        }
        __syncthreads();

        if (t < 4) {
            unsigned long long bits = s_rm[t];
            while (bits) {
                int bb = __ffsll((long long)bits) - 1;
                bits &= bits - 1ull;
                int li = t * 64 + bb;
                if (li < k) {
                    int r = s_rows[li];
                    atomicOr(&g_removed[r >> 6], 1ull << (r & 63));
                }
            }
        }
    }

    // ---- fused output emit: last block only ----
    __threadfence();
    if (t == 0) {
        unsigned v = atomicAdd(&g_doneN, 1u);
        s_isLast = (v == gridDim.x - 1) ? 1u : 0u;
    }
    __syncthreads();
    if (s_isLast) {
        if (t == 0) g_doneN = 0u;
        if (t < 64) s_snap[t] = g_removed[t];
        __syncthreads();
        if (t < 64) g_removed[t] = 0ull;   // reset for the next call

        for (int o = t; o < out_size; o += blockDim.x) {
            float v = 0.0f;
            if (o < K_TOP * 5) {
                int r = o / 5, cc = o - r * 5;
                bool keep = !((s_snap[r >> 6] >> (r & 63)) & 1ull) && (g_val[r] > 0.0f);
                if (keep) v = (cc < 4) ? g_bk[r][cc] : g_val[r];
            } else if (o < K_TOP * 6) {
                v = (float)g_label[o - K_TOP * 5];
            } else if (o < K_TOP * 7) {
                int r = o - K_TOP * 6;
                bool keep = !((s_snap[r >> 6] >> (r & 63)) & 1ull) && (g_val[r] > 0.0f);
                v = keep ? 1.0f : 0.0f;
            }
            out[o] = v;
        }
    }
}

extern "C" void kernel_launch(void* const* d_in, const int* in_sizes, int n_in,
                              void* d_out, int out_size) {
    const float* x     = (const float*)d_in[0];
    const float* boxes = (const float*)d_in[1];
    float* out = (float*)d_out;

    k_softmax<<<N_BOX / 8, 256>>>(x);
    k_rankscatter<<<HIST_N, 256>>>(boxes);
    k_nms<<<C_CLS - 1, 256>>>(out, out_size);
}

// round 16
// speedup vs baseline: 1.0234x; 1.0234x over previous
#include <cuda_runtime.h>
#include <stdint.h>

#define N_BOX 32768
#define C_CLS 81
#define K_TOP 4096
#define SCORE_T 0.05f
#define NMS_T 0.5f
#define IMG_W 1333.0f
#define IMG_H 800.0f
#define CLS_OFF 4096.0f

// p in (0.05, 1.0]  =>  float top-16 bits in [0x3D4C, 0x3F80]
#define HIST_LO 0x3D4C
#define HIST_N  565
#define BKT_CAP 2048     // max keys per 16-bit bucket (worst observed ~400)

#define NMS_CAP 256      // max rows per class (mean ~51)

// ---- device state. Invariant: every counter is zero on entry to each call
// (zero-init at load; consume-then-reset within each call thereafter).
__device__ unsigned int g_bktCnt[HIST_N];
__device__ unsigned long long g_bktKeys[HIST_N * BKT_CAP];   // 9.3 MB scratch
__device__ int g_cutBucket;
__device__ int g_base[HIST_N];     // keys in buckets strictly above b

__device__ int g_clsCnt[C_CLS];
__device__ int g_clsRows[C_CLS * NMS_CAP];

__device__ float g_bk[K_TOP][4];
__device__ float g_boff[K_TOP][4];
__device__ float g_area[K_TOP];
__device__ float g_val[K_TOP];
__device__ int   g_label[K_TOP];

__device__ unsigned long long g_removed[64];

__device__ unsigned int g_doneN;   // nms done-counter (self-resetting)

// xor-butterfly tree sum — all lanes end with identical bits (VALIDATED)
__device__ __forceinline__ float btree_add(float v) {
    #pragma unroll
    for (int o = 16; o; o >>= 1) v = __fadd_rn(v, __shfl_xor_sync(0xFFFFFFFFu, v, o));
    return v;
}

__device__ __forceinline__ void emit_cand(unsigned vb, unsigned idx) {
    int b = (int)(vb >> 16) - HIST_LO;
    unsigned pos = atomicAdd(&g_bktCnt[b], 1u);
    if (pos < BKT_CAP)
        g_bktKeys[b * BKT_CAP + pos] =
            ((unsigned long long)vb << 32) | (0xFFFFFFFFu - idx);
}

// one warp per row — bitwise model of the Triton/MLIR normalization emitter
// (VALIDATED round 6: rel_err 9.3e-12 — arithmetic is FROZEN).
// R15's fused findcut tail REVERTED: the per-block __threadfence across a
// 4096-block grid cost ~20us — far more than the launch it saved.
__global__ void k_softmax(const float* __restrict__ x) {
    int warp = (blockIdx.x * blockDim.x + threadIdx.x) >> 5;
    int lane = threadIdx.x & 31;
    if (warp >= N_BOX) return;
    const float* row = x + (size_t)warp * C_CLS;

    float v0 = row[lane];
    float v1 = row[lane + 32];
    float v2 = (lane < 17) ? row[lane + 64] : -1e30f;

    float m = fmaxf(fmaxf(v0, v1), v2);
    #pragma unroll
    for (int o = 16; o; o >>= 1) m = fmaxf(m, __shfl_xor_sync(0xFFFFFFFFu, m, o));

    float e0 = expf(__fsub_rn(v0, m));
    float e1 = expf(__fsub_rn(v1, m));
    float e2 = (lane < 17) ? expf(__fsub_rn(v2, m)) : 0.0f;

    float B0 = btree_add(e0);
    float B1 = btree_add(e1);
    float B2 = btree_add(e2);
    float s = __fadd_rn(__fadd_rn(B0, B2), B1);

    float p0 = __fdiv_rn(e0, s);
    float p1 = __fdiv_rn(e1, s);
    float p2 = __fdiv_rn(e2, s);

    unsigned rowbase = (unsigned)warp * C_CLS;
    if ((lane != 0) && (p0 > SCORE_T)) emit_cand(__float_as_uint(p0), rowbase + lane);
    if (p1 > SCORE_T)                  emit_cand(__float_as_uint(p1), rowbase + lane + 32);
    if ((lane < 17) && (p2 > SCORE_T)) emit_cand(__float_as_uint(p2), rowbase + lane + 64);
}

// suffix bases from the bucket counters (== histogram); find cut bucket.
// Does NOT reset g_bktCnt — k_rankscatter consumes then resets it.
__global__ void k_findcut() {
    __shared__ unsigned int h[HIST_N];
    int t = threadIdx.x;
    if (t < HIST_N) h[t] = g_bktCnt[t];
    __syncthreads();
    if (t == 0) {
        unsigned int acc = 0;
        int b = HIST_N - 1;
        int cut = 0;
        for (; b >= 0; b--) {
            g_base[b] = (int)acc;
            unsigned c = h[b]; if (c > BKT_CAP) c = BKT_CAP;
            acc += c;
            if (acc >= K_TOP) { cut = b; break; }
        }
        g_cutBucket = cut;
    }
}

// one CTA per bucket: exact local rank within bucket (keys unique, shared
// 16-bit prefix), global rank = base[b] + local; decode straight into the
// final sorted slot; build per-class lists.
// Consume-then-reset is race-safe: all threads read kb, __syncthreads, then
// t0 resets — before any early return.
__global__ void k_rankscatter(const float* __restrict__ boxes) {
    __shared__ unsigned long long keys[BKT_CAP];
    int b = blockIdx.x;
    int t = threadIdx.x;
    int kb = (int)g_bktCnt[b];
    __syncthreads();
    if (t == 0) g_bktCnt[b] = 0u;
    if (kb > BKT_CAP) kb = BKT_CAP;
    if (kb == 0 || b < g_cutBucket) return;
    int base = g_base[b];

    for (int i = t; i < kb; i += blockDim.x) keys[i] = g_bktKeys[b * BKT_CAP + i];
    __syncthreads();

    for (int i = t; i < kb; i += blockDim.x) {
        unsigned long long key = keys[i];
        int lr = 0;
        for (int j = 0; j < kb; j++) lr += (keys[j] > key);
        int r = base + lr;
        if (r >= K_TOP) continue;
        unsigned idx = 0xFFFFFFFFu - (unsigned)(key & 0xFFFFFFFFull);
        float val = __uint_as_float((unsigned)(key >> 32));
        int bi = (int)(idx / C_CLS);
        int lb = (int)(idx % C_CLS);
        float x1 = fminf(fmaxf(boxes[bi * 4 + 0], 0.0f), IMG_W - 1.0f);
        float y1 = fminf(fmaxf(boxes[bi * 4 + 1], 0.0f), IMG_H - 1.0f);
        float x2 = fminf(fmaxf(boxes[bi * 4 + 2], 0.0f), IMG_W - 1.0f);
        float y2 = fminf(fmaxf(boxes[bi * 4 + 3], 0.0f), IMG_H - 1.0f);
        g_bk[r][0] = x1; g_bk[r][1] = y1; g_bk[r][2] = x2; g_bk[r][3] = y2;
        g_val[r] = val; g_label[r] = lb;
        float off = __fmul_rn((float)lb, CLS_OFF);
        float ox1 = __fadd_rn(x1, off), oy1 = __fadd_rn(y1, off);
        float ox2 = __fadd_rn(x2, off), oy2 = __fadd_rn(y2, off);
        g_boff[r][0] = ox1; g_boff[r][1] = oy1; g_boff[r][2] = ox2; g_boff[r][3] = oy2;
        g_area[r] = __fmul_rn(__fsub_rn(ox2, ox1), __fsub_rn(oy2, oy1));
        int p = atomicAdd(&g_clsCnt[lb], 1);
        if (p < NMS_CAP) g_clsRows[lb * NMS_CAP + p] = r;
    }
}

// Per-class NMS (one 256-thread block per class; cross-class IoU provably 0)
// + fused output emit in the last-finishing block (80 blocks — fence cheap).
// Greedy chain iterates ONLY rows with outgoing suppression edges.
__global__ void k_nms(float* __restrict__ out, int out_size) {
    __shared__ int s_r[NMS_CAP];
    __shared__ int s_rows[NMS_CAP];
    __shared__ float s_box[NMS_CAP][4];
    __shared__ float s_area[NMS_CAP];
    __shared__ unsigned long long s_sup[NMS_CAP][4];
    __shared__ unsigned int s_has[8];
    __shared__ unsigned long long s_rm[4];
    __shared__ unsigned int s_isLast;
    __shared__ unsigned long long s_snap[64];

    int c = blockIdx.x + 1;          // classes 1..80
    int t = threadIdx.x;             // 256 threads

    int k = g_clsCnt[c];
    __syncthreads();                 // all threads read k
    if (t == 0) g_clsCnt[c] = 0;     // consume-then-reset
    if (k > NMS_CAP) k = NMS_CAP;

    if (k > 1) {                     // k uniform per block => uniform branch
        if (t < k) s_r[t] = g_clsRows[c * NMS_CAP + t];
        __syncthreads();

        // order ascending by rank (ranks unique): counting sort, 1 thread/row
        if (t < k) {
            int ri = s_r[t];
            int pos = 0;
            for (int j = 0; j < k; j++) pos += (s_r[j] < ri);
            s_rows[pos] = ri;
        }
        __syncthreads();

        if (t < k) {
            int r = s_rows[t];
            s_box[t][0] = g_boff[r][0]; s_box[t][1] = g_boff[r][1];
            s_box[t][2] = g_boff[r][2]; s_box[t][3] = g_boff[r][3];
            s_area[t] = g_area[r];
        }
        __syncthreads();

        // suppression rows (identical _rn sequence; div only when inter>0 —
        // inter==0 => iou==0 exactly => no suppression, provably identical)
        unsigned long long w0 = 0, w1 = 0, w2 = 0, w3 = 0;
        if (t < k) {
            float x1 = s_box[t][0], y1 = s_box[t][1], x2 = s_box[t][2], y2 = s_box[t][3];
            float ai = s_area[t];
            for (int j = t + 1; j < k; j++) {
                float iw = fmaxf(__fsub_rn(fminf(x2, s_box[j][2]), fmaxf(x1, s_box[j][0])), 0.0f);
                float ih = fmaxf(__fsub_rn(fminf(y2, s_box[j][3]), fmaxf(y1, s_box[j][1])), 0.0f);
                float inter = __fmul_rn(iw, ih);
                if (inter > 0.0f) {
                    float denom = __fadd_rn(__fsub_rn(__fadd_rn(ai, s_area[j]), inter), 1e-9f);
                    if (__fdiv_rn(inter, denom) > NMS_T) {
                        unsigned long long bb = 1ull << (j & 63);
                        switch (j >> 6) { case 0: w0 |= bb; break; case 1: w1 |= bb; break;
                                          case 2: w2 |= bb; break; default: w3 |= bb; break; }
                    }
                }
            }
            s_sup[t][0] = w0; s_sup[t][1] = w1; s_sup[t][2] = w2; s_sup[t][3] = w3;
        }
        bool has = ((w0 | w1 | w2 | w3) != 0ull);   // false for t >= k
        unsigned bal = __ballot_sync(0xFFFFFFFFu, has);
        if ((t & 31) == 0) s_has[t >> 5] = bal;
        __syncthreads();

        // sparse serial greedy chain (thread 0) over edge-bearing rows only
        if (t == 0) {
            unsigned long long r0 = 0, r1 = 0, r2 = 0, r3 = 0;
            for (int w8 = 0; w8 < 8; w8++) {
                unsigned bits = s_has[w8];
                while (bits) {
                    int b = __ffs(bits) - 1;
                    bits &= bits - 1u;
                    int i = w8 * 32 + b;
                    unsigned long long rw = (i < 64) ? r0 : (i < 128) ? r1 : (i < 192) ? r2 : r3;
                    if (!((rw >> (i & 63)) & 1ull)) {
                        r0 |= s_sup[i][0]; r1 |= s_sup[i][1];
                        r2 |= s_sup[i][2]; r3 |= s_sup[i][3];
                    }
                }
            }
            s_rm[0] = r0; s_rm[1] = r1; s_rm[2] = r2; s_rm[3] = r3;
        }
        __syncthreads();

        if (t < 4) {
            unsigned long long bits = s_rm[t];
            while (bits) {
                int bb = __ffsll((long long)bits) - 1;
                bits &= bits - 1ull;
                int li = t * 64 + bb;
                if (li < k) {
                    int r = s_rows[li];
                    atomicOr(&g_removed[r >> 6], 1ull << (r & 63));
                }
            }
        }
    }

    // ---- fused output emit: last block only (80 blocks — fence is cheap) ----
    __threadfence();
    if (t == 0) {
        unsigned v = atomicAdd(&g_doneN, 1u);
        s_isLast = (v == gridDim.x - 1) ? 1u : 0u;
    }
    __syncthreads();
    if (s_isLast) {
        if (t == 0) g_doneN = 0u;
        if (t < 64) s_snap[t] = g_removed[t];
        __syncthreads();
        if (t < 64) g_removed[t] = 0ull;   // reset for the next call

        for (int o = t; o < out_size; o += blockDim.x) {
            float v = 0.0f;
            if (o < K_TOP * 5) {
                int r = o / 5, cc = o - r * 5;
                bool keep = !((s_snap[r >> 6] >> (r & 63)) & 1ull) && (g_val[r] > 0.0f);
                if (keep) v = (cc < 4) ? g_bk[r][cc] : g_val[r];
            } else if (o < K_TOP * 6) {
                v = (float)g_label[o - K_TOP * 5];
            } else if (o < K_TOP * 7) {
                int r = o - K_TOP * 6;
                bool keep = !((s_snap[r >> 6] >> (r & 63)) & 1ull) && (g_val[r] > 0.0f);
                v = keep ? 1.0f : 0.0f;
            }
            out[o] = v;
        }
    }
}

extern "C" void kernel_launch(void* const* d_in, const int* in_sizes, int n_in,
                              void* d_out, int out_size) {
    const float* x     = (const float*)d_in[0];
    const float* boxes = (const float*)d_in[1];
    float* out = (float*)d_out;

    k_softmax<<<N_BOX / 8, 256>>>(x);
    k_findcut<<<1, 576>>>();
    k_rankscatter<<<HIST_N, 256>>>(boxes);
    k_nms<<<C_CLS - 1, 256>>>(out, out_size);
}

// round 17
// speedup vs baseline: 1.7049x; 1.6658x over previous
#include <cuda_runtime.h>
#include <stdint.h>

#define N_BOX 32768
#define C_CLS 81
#define K_TOP 4096
#define SCORE_T 0.05f
#define NMS_T 0.5f
#define IMG_W 1333.0f
#define IMG_H 800.0f
#define CLS_OFF 4096.0f

// p in (0.05, 1.0]  =>  float top-16 bits in [0x3D4C, 0x3F80]
#define HIST_LO 0x3D4C
#define HIST_N  565
#define BKT_CAP 2048     // max keys per 16-bit bucket (worst observed ~400)

#define NMS_CAP 256      // max rows per class (mean ~51)

// ---- device state. Counters are zero on entry to each call (zero-init at
// load; consume-then-reset thereafter). g_removed is reset at the FRONT of
// each call (k_findcut) — it may carry the previous call's bits between
// calls, but is always cleared before k_nms writes and k_out reads it.
__device__ unsigned int g_bktCnt[HIST_N];
__device__ unsigned long long g_bktKeys[HIST_N * BKT_CAP];   // 9.3 MB scratch
__device__ int g_cutBucket;
__device__ int g_base[HIST_N];     // keys in buckets strictly above b

__device__ int g_clsCnt[C_CLS];
__device__ int g_clsRows[C_CLS * NMS_CAP];

__device__ float g_bk[K_TOP][4];
__device__ float g_boff[K_TOP][4];
__device__ float g_area[K_TOP];
__device__ float g_val[K_TOP];
__device__ int   g_label[K_TOP];

__device__ unsigned long long g_removed[64];

// xor-butterfly tree sum — all lanes end with identical bits (VALIDATED)
__device__ __forceinline__ float btree_add(float v) {
    #pragma unroll
    for (int o = 16; o; o >>= 1) v = __fadd_rn(v, __shfl_xor_sync(0xFFFFFFFFu, v, o));
    return v;
}

__device__ __forceinline__ void emit_cand(unsigned vb, unsigned idx) {
    int b = (int)(vb >> 16) - HIST_LO;
    unsigned pos = atomicAdd(&g_bktCnt[b], 1u);
    if (pos < BKT_CAP)
        g_bktKeys[b * BKT_CAP + pos] =
            ((unsigned long long)vb << 32) | (0xFFFFFFFFu - idx);
}

// one warp per row — bitwise model of the Triton/MLIR normalization emitter
// (VALIDATED round 6: rel_err 9.3e-12 — arithmetic is FROZEN)
__global__ void k_softmax(const float* __restrict__ x) {
    int warp = (blockIdx.x * blockDim.x + threadIdx.x) >> 5;
    int lane = threadIdx.x & 31;
    if (warp >= N_BOX) return;
    const float* row = x + (size_t)warp * C_CLS;

    float v0 = row[lane];
    float v1 = row[lane + 32];
    float v2 = (lane < 17) ? row[lane + 64] : -1e30f;

    float m = fmaxf(fmaxf(v0, v1), v2);
    #pragma unroll
    for (int o = 16; o; o >>= 1) m = fmaxf(m, __shfl_xor_sync(0xFFFFFFFFu, m, o));

    float e0 = expf(__fsub_rn(v0, m));
    float e1 = expf(__fsub_rn(v1, m));
    float e2 = (lane < 17) ? expf(__fsub_rn(v2, m)) : 0.0f;

    float B0 = btree_add(e0);
    float B1 = btree_add(e1);
    float B2 = btree_add(e2);
    float s = __fadd_rn(__fadd_rn(B0, B2), B1);

    float p0 = __fdiv_rn(e0, s);
    float p1 = __fdiv_rn(e1, s);
    float p2 = __fdiv_rn(e2, s);

    unsigned rowbase = (unsigned)warp * C_CLS;
    if ((lane != 0) && (p0 > SCORE_T)) emit_cand(__float_as_uint(p0), rowbase + lane);
    if (p1 > SCORE_T)                  emit_cand(__float_as_uint(p1), rowbase + lane + 32);
    if ((lane < 17) && (p2 > SCORE_T)) emit_cand(__float_as_uint(p2), rowbase + lane + 64);
}

// suffix bases from the bucket counters (== histogram); find cut bucket.
// Also clears g_removed for this call (runs before k_nms writes it).
__global__ void k_findcut() {
    __shared__ unsigned int h[HIST_N];
    int t = threadIdx.x;
    if (t < HIST_N) h[t] = g_bktCnt[t];
    if (t >= HIST_N && t < HIST_N + 64) g_removed[t - HIST_N] = 0ull;
    __syncthreads();
    if (t == 0) {
        unsigned int acc = 0;
        int b = HIST_N - 1;
        int cut = 0;
        for (; b >= 0; b--) {
            g_base[b] = (int)acc;
            unsigned c = h[b]; if (c > BKT_CAP) c = BKT_CAP;
            acc += c;
            if (acc >= K_TOP) { cut = b; break; }
        }
        g_cutBucket = cut;
    }
}

// one CTA per bucket: exact local rank within bucket (keys unique, shared
// 16-bit prefix), global rank = base[b] + local; decode straight into the
// final sorted slot; build per-class lists.
// Consume-then-reset is race-safe: all threads read kb, __syncthreads, then
// t0 resets — before any early return.
__global__ void k_rankscatter(const float* __restrict__ boxes) {
    __shared__ unsigned long long keys[BKT_CAP];
    int b = blockIdx.x;
    int t = threadIdx.x;
    int kb = (int)g_bktCnt[b];
    __syncthreads();
    if (t == 0) g_bktCnt[b] = 0u;
    if (kb > BKT_CAP) kb = BKT_CAP;
    if (kb == 0 || b < g_cutBucket) return;
    int base = g_base[b];

    for (int i = t; i < kb; i += blockDim.x) keys[i] = g_bktKeys[b * BKT_CAP + i];
    __syncthreads();

    for (int i = t; i < kb; i += blockDim.x) {
        unsigned long long key = keys[i];
        int lr = 0;
        for (int j = 0; j < kb; j++) lr += (keys[j] > key);
        int r = base + lr;
        if (r >= K_TOP) continue;
        unsigned idx = 0xFFFFFFFFu - (unsigned)(key & 0xFFFFFFFFull);
        float val = __uint_as_float((unsigned)(key >> 32));
        int bi = (int)(idx / C_CLS);
        int lb = (int)(idx % C_CLS);
        float x1 = fminf(fmaxf(boxes[bi * 4 + 0], 0.0f), IMG_W - 1.0f);
        float y1 = fminf(fmaxf(boxes[bi * 4 + 1], 0.0f), IMG_H - 1.0f);
        float x2 = fminf(fmaxf(boxes[bi * 4 + 2], 0.0f), IMG_W - 1.0f);
        float y2 = fminf(fmaxf(boxes[bi * 4 + 3], 0.0f), IMG_H - 1.0f);
        g_bk[r][0] = x1; g_bk[r][1] = y1; g_bk[r][2] = x2; g_bk[r][3] = y2;
        g_val[r] = val; g_label[r] = lb;
        float off = __fmul_rn((float)lb, CLS_OFF);
        float ox1 = __fadd_rn(x1, off), oy1 = __fadd_rn(y1, off);
        float ox2 = __fadd_rn(x2, off), oy2 = __fadd_rn(y2, off);
        g_boff[r][0] = ox1; g_boff[r][1] = oy1; g_boff[r][2] = ox2; g_boff[r][3] = oy2;
        g_area[r] = __fmul_rn(__fsub_rn(ox2, ox1), __fsub_rn(oy2, oy1));
        int p = atomicAdd(&g_clsCnt[lb], 1);
        if (p < NMS_CAP) g_clsRows[lb * NMS_CAP + p] = r;
    }
}

// Per-class NMS: one 256-thread block per class (8 warps hide LDS/FDIV
// latency). Cross-class IoU provably 0 (4096-px class offset). Division only
// when inter>0 (bit-exact). Sparse greedy chain over edge-bearing rows only.
__global__ void k_nms() {
    __shared__ int s_r[NMS_CAP];
    __shared__ int s_rows[NMS_CAP];
    __shared__ float s_box[NMS_CAP][4];
    __shared__ float s_area[NMS_CAP];
    __shared__ unsigned long long s_sup[NMS_CAP][4];
    __shared__ unsigned int s_has[8];
    __shared__ unsigned long long s_rm[4];

    int c = blockIdx.x + 1;          // classes 1..80
    int t = threadIdx.x;             // 256 threads

    int k = g_clsCnt[c];
    __syncthreads();                 // all threads read k
    if (t == 0) g_clsCnt[c] = 0;     // consume-then-reset (uniform k)
    if (k > NMS_CAP) k = NMS_CAP;
    if (k <= 1) return;

    if (t < k) s_r[t] = g_clsRows[c * NMS_CAP + t];
    __syncthreads();

    // order ascending by rank (ranks unique): counting sort, one thread/row
    if (t < k) {
        int ri = s_r[t];
        int pos = 0;
        for (int j = 0; j < k; j++) pos += (s_r[j] < ri);
        s_rows[pos] = ri;
    }
    __syncthreads();

    if (t < k) {
        int r = s_rows[t];
        s_box[t][0] = g_boff[r][0]; s_box[t][1] = g_boff[r][1];
        s_box[t][2] = g_boff[r][2]; s_box[t][3] = g_boff[r][3];
        s_area[t] = g_area[r];
    }
    __syncthreads();

    // suppression rows (identical _rn sequence; div only when inter>0 —
    // inter==0 => iou==0 exactly => no suppression, provably identical)
    unsigned long long w0 = 0, w1 = 0, w2 = 0, w3 = 0;
    if (t < k) {
        float x1 = s_box[t][0], y1 = s_box[t][1], x2 = s_box[t][2], y2 = s_box[t][3];
        float ai = s_area[t];
        for (int j = t + 1; j < k; j++) {
            float iw = fmaxf(__fsub_rn(fminf(x2, s_box[j][2]), fmaxf(x1, s_box[j][0])), 0.0f);
            float ih = fmaxf(__fsub_rn(fminf(y2, s_box[j][3]), fmaxf(y1, s_box[j][1])), 0.0f);
            float inter = __fmul_rn(iw, ih);
            if (inter > 0.0f) {
                float denom = __fadd_rn(__fsub_rn(__fadd_rn(ai, s_area[j]), inter), 1e-9f);
                if (__fdiv_rn(inter, denom) > NMS_T) {
                    unsigned long long bb = 1ull << (j & 63);
                    switch (j >> 6) { case 0: w0 |= bb; break; case 1: w1 |= bb; break;
                                      case 2: w2 |= bb; break; default: w3 |= bb; break; }
                }
            }
        }
        s_sup[t][0] = w0; s_sup[t][1] = w1; s_sup[t][2] = w2; s_sup[t][3] = w3;
    }
    bool has = ((w0 | w1 | w2 | w3) != 0ull);   // false for t >= k
    unsigned bal = __ballot_sync(0xFFFFFFFFu, has);
    if ((t & 31) == 0) s_has[t >> 5] = bal;
    __syncthreads();

    // sparse serial greedy chain (thread 0) over edge-bearing rows only
    if (t == 0) {
        unsigned long long r0 = 0, r1 = 0, r2 = 0, r3 = 0;
        for (int w8 = 0; w8 < 8; w8++) {
            unsigned bits = s_has[w8];
            while (bits) {
                int b = __ffs(bits) - 1;
                bits &= bits - 1u;
                int i = w8 * 32 + b;
                unsigned long long rw = (i < 64) ? r0 : (i < 128) ? r1 : (i < 192) ? r2 : r3;
                if (!((rw >> (i & 63)) & 1ull)) {
                    r0 |= s_sup[i][0]; r1 |= s_sup[i][1];
                    r2 |= s_sup[i][2]; r3 |= s_sup[i][3];
                }
            }
        }
        s_rm[0] = r0; s_rm[1] = r1; s_rm[2] = r2; s_rm[3] = r3;
    }
    __syncthreads();

    if (t < 4) {
        unsigned long long bits = s_rm[t];
        while (bits) {
            int bb = __ffsll((long long)bits) - 1;
            bits &= bits - 1ull;
            int li = t * 64 + bb;
            if (li < k) {
                int r = s_rows[li];
                atomicOr(&g_removed[r >> 6], 1ull << (r & 63));
            }
        }
    }
}

// chip-wide output emit: one 256-element chunk per block (112 blocks — full
// MLP across SMs). g_removed is read-only here; it's cleared next call by
// k_findcut. Layout: dets[4096*5], labels[4096], keep[4096].
__global__ void k_out(float* __restrict__ out, int out_size) {
    int o = blockIdx.x * blockDim.x + threadIdx.x;
    if (o >= out_size) return;
    float v = 0.0f;
    if (o < K_TOP * 5) {
        int r = o / 5, cc = o - r * 5;
        bool keep = !((g_removed[r >> 6] >> (r & 63)) & 1ull) && (g_val[r] > 0.0f);
        if (keep) v = (cc < 4) ? g_bk[r][cc] : g_val[r];
    } else if (o < K_TOP * 6) {
        v = (float)g_label[o - K_TOP * 5];
    } else if (o < K_TOP * 7) {
        int r = o - K_TOP * 6;
        bool keep = !((g_removed[r >> 6] >> (r & 63)) & 1ull) && (g_val[r] > 0.0f);
        v = keep ? 1.0f : 0.0f;
    }
    out[o] = v;
}

extern "C" void kernel_launch(void* const* d_in, const int* in_sizes, int n_in,
                              void* d_out, int out_size) {
    const float* x     = (const float*)d_in[0];
    const float* boxes = (const float*)d_in[1];
    float* out = (float*)d_out;

    k_softmax<<<N_BOX / 8, 256>>>(x);
    k_findcut<<<1, 640>>>();
    k_rankscatter<<<HIST_N, 256>>>(boxes);
    k_nms<<<C_CLS - 1, 256>>>();
    int nblk = (out_size + 255) / 256;
    k_out<<<nblk, 256>>>(out, out_size);
}